// round 9
// baseline (speedup 1.0000x reference)
#include <cuda_runtime.h>
#include <cuda_bf16.h>
#include <cstdint>

// ---------------------------------------------------------------------------
// ToyTransformerBlock: B=2, T=2048, D=2048, H=16, Dh=128, F=8192, fp32 I/O
// Round 8: bf16x3 pre-split operands + 4-stage BK=16 cp.async pipeline with
//          a single __syncthreads per K-step (RSTRIDE=48 conflict-free).
// ---------------------------------------------------------------------------

#define B_   2
#define T_   2048
#define D_   2048
#define H_   16
#define DH_  128
#define F_   8192
#define MTOK (B_ * T_)
#define LN_EPS 1e-5f

typedef __nv_bfloat16 bf16;

// ------------------------- scratch (device globals) ------------------------
__device__ bf16 g_wqh[(size_t)D_ * D_], g_wql[(size_t)D_ * D_];
__device__ bf16 g_wkh[(size_t)D_ * D_], g_wkl[(size_t)D_ * D_];
__device__ bf16 g_wvh[(size_t)D_ * D_], g_wvl[(size_t)D_ * D_];
__device__ bf16 g_woh[(size_t)D_ * D_], g_wol[(size_t)D_ * D_];
__device__ bf16 g_wgh[(size_t)F_ * D_], g_wgl[(size_t)F_ * D_];
__device__ bf16 g_wuh[(size_t)F_ * D_], g_wul[(size_t)F_ * D_];
__device__ bf16 g_wdh[(size_t)D_ * F_], g_wdl[(size_t)D_ * F_];
__device__ bf16 g_xnh[(size_t)MTOK * D_], g_xnl[(size_t)MTOK * D_];
__device__ bf16 g_qh [(size_t)MTOK * D_], g_ql [(size_t)MTOK * D_];
__device__ bf16 g_kh [(size_t)MTOK * D_], g_kl [(size_t)MTOK * D_];
__device__ bf16 g_vh [(size_t)MTOK * D_], g_vl [(size_t)MTOK * D_];
__device__ bf16 g_vth[(size_t)MTOK * D_], g_vtl[(size_t)MTOK * D_];   // [b,h,d,t]
__device__ bf16 g_ath[(size_t)MTOK * D_], g_atl[(size_t)MTOK * D_];
__device__ bf16 g_hh [(size_t)MTOK * F_], g_hl [(size_t)MTOK * F_];
__device__ bf16 g_ph [(size_t)B_ * H_ * T_ * T_];
__device__ bf16 g_pl [(size_t)B_ * H_ * T_ * T_];
__device__ float g_s  [(size_t)B_ * H_ * T_ * T_];
__device__ float g_x1 [(size_t)MTOK * D_];
__device__ float g_gate[(size_t)MTOK * F_];
__device__ float g_up  [(size_t)MTOK * F_];

// ------------------------------ helpers ------------------------------------
__device__ __forceinline__ uint32_t smem_u32(const void* p) {
    uint32_t a;
    asm("{ .reg .u64 t; cvta.to.shared.u64 t, %1; cvt.u32.u64 %0, t; }"
        : "=r"(a) : "l"(p));
    return a;
}
__device__ __forceinline__ void ldm4(uint32_t addr, uint32_t* r) {
    asm volatile("ldmatrix.sync.aligned.m8n8.x4.shared.b16 {%0,%1,%2,%3}, [%4];"
        : "=r"(r[0]), "=r"(r[1]), "=r"(r[2]), "=r"(r[3]) : "r"(addr));
}
__device__ __forceinline__ void mma16816(float* c, const uint32_t* a,
                                         const uint32_t* b) {
    asm volatile(
        "mma.sync.aligned.m16n8k16.row.col.f32.bf16.bf16.f32 "
        "{%0,%1,%2,%3}, {%4,%5,%6,%7}, {%8,%9}, {%0,%1,%2,%3};"
        : "+f"(c[0]), "+f"(c[1]), "+f"(c[2]), "+f"(c[3])
        : "r"(a[0]), "r"(a[1]), "r"(a[2]), "r"(a[3]), "r"(b[0]), "r"(b[1]));
}
#define CP16(sm, gm) \
    asm volatile("cp.async.cg.shared.global [%0], [%1], 16;" :: "r"(sm), "l"(gm))
#define CPCOMMIT() asm volatile("cp.async.commit_group;" ::: "memory")
#define CPWAIT(n)  asm volatile("cp.async.wait_group %0;" :: "n"(n) : "memory")

__device__ __forceinline__ uint32_t bfu(bf16 h) {
    return (uint32_t)__bfloat16_as_ushort(h);
}
__device__ __forceinline__ void split1(float v, bf16& h, bf16& l) {
    h = __float2bfloat16_rn(v);
    l = __float2bfloat16_rn(v - __bfloat162float(h));
}
__device__ __forceinline__ void split2(float a, float b, uint32_t& hp, uint32_t& lp) {
    bf16 ha, la, hb, lb;
    split1(a, ha, la); split1(b, hb, lb);
    hp = (bfu(hb) << 16) | bfu(ha);
    lp = (bfu(lb) << 16) | bfu(la);
}

// ------------------------- bf16x3 TN GEMM kernel ---------------------------
// C[128x128 tile] = alpha * (Ah+Al)[M,K] x (Bh+Bl)[N,K]^T
//   EPI 0: C fp32 * alpha ; EPI 1: C fp32 + R ; EPI 2: C -> bf16 hi/lo
// Stage (BK=16): 4 tiles (Ah, Al, Bh, Bl) of 128 rows x 48B (32B data + pad).
// RSTRIDE=48: bank walk 12r mod 32 over 8 rows is a disjoint cover -> ldmatrix
// conflict-free. 4 stages, single __syncthreads per K-step.
static constexpr int RSTRIDE   = 48;
static constexpr int TILE_B    = 128 * RSTRIDE;   // 6144
static constexpr int STAGE_B   = 4 * TILE_B;      // 24576
static constexpr int NSTAGE    = 4;
static constexpr int GEMM_SMEM = NSTAGE * STAGE_B; // 98304

template<int EPI>
__global__ void __launch_bounds__(256, 2)
gemm_bf3(const bf16* __restrict__ Ah, const bf16* __restrict__ Al,
         const bf16* __restrict__ Bh, const bf16* __restrict__ Bl,
         const float* __restrict__ R, float* __restrict__ C,
         bf16* __restrict__ Ch, bf16* __restrict__ Cl,
         int K, int lda, int ldb, int ldc,
         int64_t sA1, int64_t sA2, int64_t sB1, int64_t sB2,
         int64_t sC1, int64_t sC2, int nz2, float alpha)
{
    extern __shared__ uint8_t sm[];
    uint32_t smb = smem_u32(sm);

    int tid  = threadIdx.x;
    int lane = tid & 31;
    int w    = tid >> 5;
    int wm   = w & 1;          // 2 m-blocks of 64
    int wn   = w >> 1;         // 4 n-blocks of 32

    int z = blockIdx.z, z1 = z / nz2, z2 = z - z1 * nz2;
    int64_t offA = z1 * sA1 + z2 * sA2;
    int64_t offB = z1 * sB1 + z2 * sB2;
    int64_t offC = z1 * sC1 + z2 * sC2;

    int64_t rowBase = (int64_t)blockIdx.y * 128;
    int64_t colBase = (int64_t)blockIdx.x * 128;

    // staging: one CP16 per tile per thread: row = tid>>1, chunk = tid&1
    int srow = tid >> 1, sc = tid & 1;
    const bf16* AhP = Ah + offA + (rowBase + srow) * lda + sc * 8;
    const bf16* AlP = Al + offA + (rowBase + srow) * lda + sc * 8;
    const bf16* BhP = Bh + offB + (colBase + srow) * ldb + sc * 8;
    const bf16* BlP = Bl + offB + (colBase + srow) * ldb + sc * 8;
    uint32_t sOff = (uint32_t)(srow * RSTRIDE + sc * 16);

    // ldmatrix row offsets (within a tile)
    uint32_t aRowOff = (uint32_t)((wm * 64 + (lane & 15)) * RSTRIDE
                                  + ((lane >> 4) & 1) * 16);
    uint32_t bRowOff = (uint32_t)((wn * 32 + (lane & 7) + ((lane >> 4) & 1) * 8) * RSTRIDE
                                  + ((lane >> 3) & 1) * 16);

    float acc[4][4][4];
    #pragma unroll
    for (int i = 0; i < 4; i++)
        #pragma unroll
        for (int j = 0; j < 4; j++)
            #pragma unroll
            for (int e = 0; e < 4; e++) acc[i][j][e] = 0.f;

    int nT = K / 16;

    auto issue_stage = [&](int t) {
        uint32_t sb = smb + (t & 3) * STAGE_B;
        int kk0 = t * 16;
        CP16(sb + sOff,              AhP + kk0);
        CP16(sb + TILE_B + sOff,     AlP + kk0);
        CP16(sb + 2 * TILE_B + sOff, BhP + kk0);
        CP16(sb + 3 * TILE_B + sOff, BlP + kk0);
        CPCOMMIT();
    };

    // compute one BK=16 stage: {hi*hi, hi*lo, lo*hi}
    auto compute = [&](int buf) {
        uint32_t stB = smb + buf * STAGE_B;
        uint32_t aAd = stB + aRowOff;
        uint32_t bAd = stB + 2 * TILE_B + bRowOff;
        uint32_t aF[16], bH[8], bL[8];
        ldm4(aAd,           aF);
        ldm4(aAd + 1 * 768, aF + 4);
        ldm4(aAd + 2 * 768, aF + 8);
        ldm4(aAd + 3 * 768, aF + 12);
        ldm4(bAd,       bH);
        ldm4(bAd + 768, bH + 4);
        #pragma unroll
        for (int i = 0; i < 4; i++)
            #pragma unroll
            for (int j = 0; j < 4; j++)
                mma16816(acc[i][j], aF + 4 * i, bH + 2 * j);
        ldm4(bAd + TILE_B,       bL);
        ldm4(bAd + TILE_B + 768, bL + 4);
        #pragma unroll
        for (int i = 0; i < 4; i++)
            #pragma unroll
            for (int j = 0; j < 4; j++)
                mma16816(acc[i][j], aF + 4 * i, bL + 2 * j);
        ldm4(aAd + TILE_B,           aF);
        ldm4(aAd + TILE_B + 1 * 768, aF + 4);
        ldm4(aAd + TILE_B + 2 * 768, aF + 8);
        ldm4(aAd + TILE_B + 3 * 768, aF + 12);
        #pragma unroll
        for (int i = 0; i < 4; i++)
            #pragma unroll
            for (int j = 0; j < 4; j++)
                mma16816(acc[i][j], aF + 4 * i, bH + 2 * j);
    };

    // ---- 4-stage pipeline, one barrier per iteration ----
    issue_stage(0);
    issue_stage(1);
    issue_stage(2);
    for (int t = 0; t < nT; t++) {
        if (t + 2 < nT)      { CPWAIT(2); }
        else if (t + 1 < nT) { CPWAIT(1); }
        else                 { CPWAIT(0); }
        __syncthreads();     // stage t visible; all done reading stage t-1
        if (t + 3 < nT) issue_stage(t + 3);   // overwrites stage t-1: safe
        compute(t & 3);
    }

    // ---- epilogue ----
    int lrow = lane >> 2;
    int lcol = (lane & 3) * 2;
    #pragma unroll
    for (int i = 0; i < 4; i++) {
        int64_t r0 = rowBase + wm * 64 + i * 16 + lrow;
        #pragma unroll
        for (int j = 0; j < 4; j++) {
            int64_t c = colBase + wn * 32 + j * 8 + lcol;
            int64_t o0 = (offC + r0 * ldc + c);
            int64_t o1 = o0 + 8 * ldc;
            if (EPI == 0) {
                float2 p0, p1;
                p0.x = acc[i][j][0] * alpha; p0.y = acc[i][j][1] * alpha;
                p1.x = acc[i][j][2] * alpha; p1.y = acc[i][j][3] * alpha;
                *(float2*)(C + o0) = p0;
                *(float2*)(C + o1) = p1;
            } else if (EPI == 1) {
                float2 ra = *(const float2*)(R + o0);
                float2 rb = *(const float2*)(R + o1);
                float2 p0, p1;
                p0.x = acc[i][j][0] + ra.x; p0.y = acc[i][j][1] + ra.y;
                p1.x = acc[i][j][2] + rb.x; p1.y = acc[i][j][3] + rb.y;
                *(float2*)(C + o0) = p0;
                *(float2*)(C + o1) = p1;
            } else {
                uint32_t hp, lp;
                split2(acc[i][j][0], acc[i][j][1], hp, lp);
                *(uint32_t*)(Ch + o0) = hp;
                *(uint32_t*)(Cl + o0) = lp;
                split2(acc[i][j][2], acc[i][j][3], hp, lp);
                *(uint32_t*)(Ch + o1) = hp;
                *(uint32_t*)(Cl + o1) = lp;
            }
        }
    }
}

// ------------------------------ reductions ---------------------------------
__device__ __forceinline__ float warp_sum(float v) {
    #pragma unroll
    for (int o = 16; o > 0; o >>= 1) v += __shfl_xor_sync(0xffffffffu, v, o);
    return v;
}
__device__ __forceinline__ float warp_max(float v) {
    #pragma unroll
    for (int o = 16; o > 0; o >>= 1) v = fmaxf(v, __shfl_xor_sync(0xffffffffu, v, o));
    return v;
}

// ------------------------- weight split (fp32 -> hi/lo) --------------------
__global__ void __launch_bounds__(256)
split_kernel(const float* __restrict__ in, bf16* __restrict__ oh,
             bf16* __restrict__ ol)
{
    size_t i = ((size_t)blockIdx.x * 256 + threadIdx.x) * 4;
    float4 v = *(const float4*)(in + i);
    uint32_t h0, l0, h1, l1;
    split2(v.x, v.y, h0, l0);
    split2(v.z, v.w, h1, l1);
    *(uint2*)(oh + i) = make_uint2(h0, h1);
    *(uint2*)(ol + i) = make_uint2(l0, l1);
}

// ------------------------------- LayerNorm ---------------------------------
__global__ void __launch_bounds__(256)
ln_kernel(const float* __restrict__ x, const float* __restrict__ w,
          const float* __restrict__ b, bf16* __restrict__ yh,
          bf16* __restrict__ yl)
{
    __shared__ float s1[8], s2[8];
    size_t row = blockIdx.x;
    const float* xr = x + row * (size_t)D_;

    float vals[8];
    float sum = 0.f, sq = 0.f;
    #pragma unroll
    for (int i = 0; i < 8; i++) {
        float v = xr[threadIdx.x + i * 256];
        vals[i] = v; sum += v; sq += v * v;
    }
    sum = warp_sum(sum); sq = warp_sum(sq);
    int wi = threadIdx.x >> 5, li = threadIdx.x & 31;
    if (li == 0) { s1[wi] = sum; s2[wi] = sq; }
    __syncthreads();
    float ts = 0.f, tq = 0.f;
    #pragma unroll
    for (int i = 0; i < 8; i++) { ts += s1[i]; tq += s2[i]; }
    float mean = ts * (1.f / D_);
    float var  = tq * (1.f / D_) - mean * mean;
    float rstd = rsqrtf(var + LN_EPS);
    #pragma unroll
    for (int i = 0; i < 8; i++) {
        int c = threadIdx.x + i * 256;
        float y = (vals[i] - mean) * rstd * w[c] + b[c];
        bf16 h, l; split1(y, h, l);
        yh[row * (size_t)D_ + c] = h;
        yl[row * (size_t)D_ + c] = l;
    }
}

// ------------------------------- Softmax -----------------------------------
__global__ void __launch_bounds__(256)
softmax_kernel(const float* __restrict__ s, bf16* __restrict__ ph,
               bf16* __restrict__ pl)
{
    __shared__ float sm1[8], sm2[8];
    size_t row = blockIdx.x;
    const float* p = s + row * (size_t)T_;

    float v[8];
    float mx = -1e30f;
    #pragma unroll
    for (int i = 0; i < 8; i++) { v[i] = p[threadIdx.x + i * 256]; mx = fmaxf(mx, v[i]); }
    mx = warp_max(mx);
    int wi = threadIdx.x >> 5, li = threadIdx.x & 31;
    if (li == 0) sm1[wi] = mx;
    __syncthreads();
    float tmx = -1e30f;
    #pragma unroll
    for (int i = 0; i < 8; i++) tmx = fmaxf(tmx, sm1[i]);

    float sum = 0.f;
    #pragma unroll
    for (int i = 0; i < 8; i++) { v[i] = __expf(v[i] - tmx); sum += v[i]; }
    sum = warp_sum(sum);
    if (li == 0) sm2[wi] = sum;
    __syncthreads();
    float tsum = 0.f;
    #pragma unroll
    for (int i = 0; i < 8; i++) tsum += sm2[i];
    float inv = 1.f / tsum;
    #pragma unroll
    for (int i = 0; i < 8; i++) {
        int c = threadIdx.x + i * 256;
        bf16 h, l; split1(v[i] * inv, h, l);
        ph[row * (size_t)T_ + c] = h;
        pl[row * (size_t)T_ + c] = l;
    }
}

// ------------------------------ SiLU * up ----------------------------------
__global__ void __launch_bounds__(256)
silu_mul_kernel(const float* __restrict__ g, const float* __restrict__ u,
                bf16* __restrict__ hh, bf16* __restrict__ hl)
{
    size_t i = ((size_t)blockIdx.x * 256 + threadIdx.x) * 4;
    float4 gg = *(const float4*)(g + i);
    float4 uu = *(const float4*)(u + i);
    float4 o;
    o.x = gg.x * (1.f / (1.f + __expf(-gg.x))) * uu.x;
    o.y = gg.y * (1.f / (1.f + __expf(-gg.y))) * uu.y;
    o.z = gg.z * (1.f / (1.f + __expf(-gg.z))) * uu.z;
    o.w = gg.w * (1.f / (1.f + __expf(-gg.w))) * uu.w;
    uint32_t h0, l0, h1, l1;
    split2(o.x, o.y, h0, l0);
    split2(o.z, o.w, h1, l1);
    *(uint2*)(hh + i) = make_uint2(h0, h1);
    *(uint2*)(hl + i) = make_uint2(l0, l1);
}

// --------------------------- V transpose -----------------------------------
__global__ void __launch_bounds__(256)
transpose_v_kernel(const bf16* __restrict__ vh, const bf16* __restrict__ vl,
                   bf16* __restrict__ vth, bf16* __restrict__ vtl)
{
    __shared__ bf16 th[32][33], tl[32][33];
    int t0 = blockIdx.x * 32;
    int d0 = blockIdx.y * 32;
    int bb = blockIdx.z;
    int tx = threadIdx.x & 31, ty = threadIdx.x >> 5;  // 32 x 8

    #pragma unroll
    for (int kq = 0; kq < 4; kq++) {
        int y = ty + kq * 8;     // local t
        size_t gi = ((size_t)bb * T_ + t0 + y) * D_ + d0 + tx;
        th[y][tx] = vh[gi];
        tl[y][tx] = vl[gi];
    }
    __syncthreads();
    #pragma unroll
    for (int kq = 0; kq < 4; kq++) {
        int y = ty + kq * 8;     // local d
        int d = d0 + y;
        int h = d >> 7, dd = d & 127;
        size_t go = (((size_t)bb * H_ + h) * 128 + dd) * T_ + t0 + tx;
        vth[go] = th[tx][y];
        vtl[go] = tl[tx][y];
    }
}

// ------------------------------ launcher -----------------------------------
extern "C" void kernel_launch(void* const* d_in, const int* in_sizes, int n_in,
                              void* d_out, int out_size)
{
    const float* x    = (const float*)d_in[0];
    const float* wq   = (const float*)d_in[1];
    const float* wk   = (const float*)d_in[2];
    const float* wv   = (const float*)d_in[3];
    const float* wo   = (const float*)d_in[4];
    const float* wgt  = (const float*)d_in[5];
    const float* wup  = (const float*)d_in[6];
    const float* wdn  = (const float*)d_in[7];
    const float* ln1w = (const float*)d_in[8];
    const float* ln1b = (const float*)d_in[9];
    const float* ln2w = (const float*)d_in[10];
    const float* ln2b = (const float*)d_in[11];
    float* out = (float*)d_out;

    bf16 *wqh, *wql, *wkh, *wkl, *wvh, *wvl, *woh, *wol;
    bf16 *wgh, *wgl, *wuh, *wul, *wdh, *wdl;
    bf16 *xnh, *xnl, *qh, *ql, *kh, *kl, *vh, *vl, *vth, *vtl;
    bf16 *ath, *atl, *hh, *hl, *ph, *pl;
    float *s, *x1, *gate, *up;
    cudaGetSymbolAddress((void**)&wqh, g_wqh); cudaGetSymbolAddress((void**)&wql, g_wql);
    cudaGetSymbolAddress((void**)&wkh, g_wkh); cudaGetSymbolAddress((void**)&wkl, g_wkl);
    cudaGetSymbolAddress((void**)&wvh, g_wvh); cudaGetSymbolAddress((void**)&wvl, g_wvl);
    cudaGetSymbolAddress((void**)&woh, g_woh); cudaGetSymbolAddress((void**)&wol, g_wol);
    cudaGetSymbolAddress((void**)&wgh, g_wgh); cudaGetSymbolAddress((void**)&wgl, g_wgl);
    cudaGetSymbolAddress((void**)&wuh, g_wuh); cudaGetSymbolAddress((void**)&wul, g_wul);
    cudaGetSymbolAddress((void**)&wdh, g_wdh); cudaGetSymbolAddress((void**)&wdl, g_wdl);
    cudaGetSymbolAddress((void**)&xnh, g_xnh); cudaGetSymbolAddress((void**)&xnl, g_xnl);
    cudaGetSymbolAddress((void**)&qh,  g_qh);  cudaGetSymbolAddress((void**)&ql,  g_ql);
    cudaGetSymbolAddress((void**)&kh,  g_kh);  cudaGetSymbolAddress((void**)&kl,  g_kl);
    cudaGetSymbolAddress((void**)&vh,  g_vh);  cudaGetSymbolAddress((void**)&vl,  g_vl);
    cudaGetSymbolAddress((void**)&vth, g_vth); cudaGetSymbolAddress((void**)&vtl, g_vtl);
    cudaGetSymbolAddress((void**)&ath, g_ath); cudaGetSymbolAddress((void**)&atl, g_atl);
    cudaGetSymbolAddress((void**)&hh,  g_hh);  cudaGetSymbolAddress((void**)&hl,  g_hl);
    cudaGetSymbolAddress((void**)&ph,  g_ph);  cudaGetSymbolAddress((void**)&pl,  g_pl);
    cudaGetSymbolAddress((void**)&s,   g_s);   cudaGetSymbolAddress((void**)&x1,  g_x1);
    cudaGetSymbolAddress((void**)&gate, g_gate); cudaGetSymbolAddress((void**)&up, g_up);

    cudaFuncSetAttribute(gemm_bf3<0>, cudaFuncAttributeMaxDynamicSharedMemorySize, GEMM_SMEM);
    cudaFuncSetAttribute(gemm_bf3<1>, cudaFuncAttributeMaxDynamicSharedMemorySize, GEMM_SMEM);
    cudaFuncSetAttribute(gemm_bf3<2>, cudaFuncAttributeMaxDynamicSharedMemorySize, GEMM_SMEM);

    const int64_t TD = (int64_t)T_ * D_;
    const int64_t TT = (int64_t)T_ * T_;

    // 0. split weights
    split_kernel<<<(int)((size_t)D_ * D_ / 1024), 256>>>(wq,  wqh, wql);
    split_kernel<<<(int)((size_t)D_ * D_ / 1024), 256>>>(wk,  wkh, wkl);
    split_kernel<<<(int)((size_t)D_ * D_ / 1024), 256>>>(wv,  wvh, wvl);
    split_kernel<<<(int)((size_t)D_ * D_ / 1024), 256>>>(wo,  woh, wol);
    split_kernel<<<(int)((size_t)F_ * D_ / 1024), 256>>>(wgt, wgh, wgl);
    split_kernel<<<(int)((size_t)F_ * D_ / 1024), 256>>>(wup, wuh, wul);
    split_kernel<<<(int)((size_t)D_ * F_ / 1024), 256>>>(wdn, wdh, wdl);

    // 1. LN1
    ln_kernel<<<MTOK, 256>>>(x, ln1w, ln1b, xnh, xnl);

    // 2-4. Q/K/V projections
    {
        dim3 grid(D_ / 128, MTOK / 128, 1);
        gemm_bf3<2><<<grid, 256, GEMM_SMEM>>>(xnh, xnl, wqh, wql, nullptr, nullptr,
            qh, ql, D_, D_, D_, D_, 0, 0, 0, 0, 0, 0, 1, 1.f);
        gemm_bf3<2><<<grid, 256, GEMM_SMEM>>>(xnh, xnl, wkh, wkl, nullptr, nullptr,
            kh, kl, D_, D_, D_, D_, 0, 0, 0, 0, 0, 0, 1, 1.f);
        gemm_bf3<2><<<grid, 256, GEMM_SMEM>>>(xnh, xnl, wvh, wvl, nullptr, nullptr,
            vh, vl, D_, D_, D_, D_, 0, 0, 0, 0, 0, 0, 1, 1.f);
    }

    // 4b. transpose V -> [b,h,d,t]
    {
        dim3 grid(T_ / 32, D_ / 32, B_);
        transpose_v_kernel<<<grid, 256>>>(vh, vl, vth, vtl);
    }

    // 5. scores = Q K^T / sqrt(Dh)
    {
        dim3 grid(T_ / 128, T_ / 128, B_ * H_);
        gemm_bf3<0><<<grid, 256, GEMM_SMEM>>>(qh, ql, kh, kl, nullptr, s,
            nullptr, nullptr, DH_, D_, D_, T_,
            TD, DH_, TD, DH_, (int64_t)H_ * TT, TT, H_,
            0.08838834764831845f);
    }

    // 6. softmax
    softmax_kernel<<<B_ * H_ * T_, 256>>>(s, ph, pl);

    // 7. attn_out = P @ V (TN with vt)
    {
        dim3 grid(1, T_ / 128, B_ * H_);
        gemm_bf3<2><<<grid, 256, GEMM_SMEM>>>(ph, pl, vth, vtl, nullptr, nullptr,
            ath, atl, T_, T_, T_, D_,
            (int64_t)H_ * TT, TT, (int64_t)H_ * DH_ * T_, (int64_t)DH_ * T_,
            TD, DH_, H_, 1.f);
    }

    // 8. x1 = at @ wo^T + x
    {
        dim3 grid(D_ / 128, MTOK / 128, 1);
        gemm_bf3<1><<<grid, 256, GEMM_SMEM>>>(ath, atl, woh, wol, x, x1,
            nullptr, nullptr, D_, D_, D_, D_, 0, 0, 0, 0, 0, 0, 1, 1.f);
    }

    // 9. LN2
    ln_kernel<<<MTOK, 256>>>(x1, ln2w, ln2b, xnh, xnl);

    // 10-11. gate / up
    {
        dim3 grid(F_ / 128, MTOK / 128, 1);
        gemm_bf3<0><<<grid, 256, GEMM_SMEM>>>(xnh, xnl, wgh, wgl, nullptr, gate,
            nullptr, nullptr, D_, D_, D_, F_, 0, 0, 0, 0, 0, 0, 1, 1.f);
        gemm_bf3<0><<<grid, 256, GEMM_SMEM>>>(xnh, xnl, wuh, wul, nullptr, up,
            nullptr, nullptr, D_, D_, D_, F_, 0, 0, 0, 0, 0, 0, 1, 1.f);
    }

    // 12. h = silu(gate) * up
    silu_mul_kernel<<<(int)(((size_t)MTOK * F_) / 1024), 256>>>(gate, up, hh, hl);

    // 13. out = h @ wdn^T + x1
    {
        dim3 grid(D_ / 128, MTOK / 128, 1);
        gemm_bf3<1><<<grid, 256, GEMM_SMEM>>>(hh, hl, wdh, wdl, x1, out,
            nullptr, nullptr, F_, F_, F_, D_, 0, 0, 0, 0, 0, 0, 1, 1.f);
    }
}

// round 10
// speedup vs baseline: 1.8125x; 1.8125x over previous
#include <cuda_runtime.h>
#include <cuda_bf16.h>
#include <cstdint>

// ---------------------------------------------------------------------------
// ToyTransformerBlock: B=2, T=2048, D=2048, H=16, Dh=128, F=8192, fp32 I/O
// Round 9: revert to R8 GEMM (BK=32, 2-stage, RSTRIDE=80 — proven 5.52ms),
//          fuse QKV into one GEMM and gate+up into one GEMM to kill
//          wave-quantization tails.
// ---------------------------------------------------------------------------

#define B_   2
#define T_   2048
#define D_   2048
#define H_   16
#define DH_  128
#define F_   8192
#define MTOK (B_ * T_)
#define LN_EPS 1e-5f

typedef __nv_bfloat16 bf16;

// ------------------------- scratch (device globals) ------------------------
// fused weights (hi/lo bf16)
__device__ bf16 g_wqkvh[(size_t)3 * D_ * D_], g_wqkvl[(size_t)3 * D_ * D_];
__device__ bf16 g_woh  [(size_t)D_ * D_],     g_wol  [(size_t)D_ * D_];
__device__ bf16 g_wguh [(size_t)2 * F_ * D_], g_wgul [(size_t)2 * F_ * D_];
__device__ bf16 g_wdh  [(size_t)D_ * F_],     g_wdl  [(size_t)D_ * F_];
// activations
__device__ bf16 g_xnh [(size_t)MTOK * D_],     g_xnl [(size_t)MTOK * D_];
__device__ bf16 g_qkvh[(size_t)MTOK * 3 * D_], g_qkvl[(size_t)MTOK * 3 * D_];
__device__ bf16 g_vth [(size_t)MTOK * D_],     g_vtl [(size_t)MTOK * D_];   // [b,h,d,t]
__device__ bf16 g_ath [(size_t)MTOK * D_],     g_atl [(size_t)MTOK * D_];
__device__ bf16 g_hh  [(size_t)MTOK * F_],     g_hl  [(size_t)MTOK * F_];
__device__ bf16 g_ph  [(size_t)B_ * H_ * T_ * T_];
__device__ bf16 g_pl  [(size_t)B_ * H_ * T_ * T_];
__device__ float g_s  [(size_t)B_ * H_ * T_ * T_];
__device__ float g_x1 [(size_t)MTOK * D_];
__device__ float g_gu [(size_t)MTOK * 2 * F_];

// ------------------------------ helpers ------------------------------------
__device__ __forceinline__ uint32_t smem_u32(const void* p) {
    uint32_t a;
    asm("{ .reg .u64 t; cvta.to.shared.u64 t, %1; cvt.u32.u64 %0, t; }"
        : "=r"(a) : "l"(p));
    return a;
}
__device__ __forceinline__ void ldm4(uint32_t addr, uint32_t* r) {
    asm volatile("ldmatrix.sync.aligned.m8n8.x4.shared.b16 {%0,%1,%2,%3}, [%4];"
        : "=r"(r[0]), "=r"(r[1]), "=r"(r[2]), "=r"(r[3]) : "r"(addr));
}
__device__ __forceinline__ void mma16816(float* c, const uint32_t* a,
                                         const uint32_t* b) {
    asm volatile(
        "mma.sync.aligned.m16n8k16.row.col.f32.bf16.bf16.f32 "
        "{%0,%1,%2,%3}, {%4,%5,%6,%7}, {%8,%9}, {%0,%1,%2,%3};"
        : "+f"(c[0]), "+f"(c[1]), "+f"(c[2]), "+f"(c[3])
        : "r"(a[0]), "r"(a[1]), "r"(a[2]), "r"(a[3]), "r"(b[0]), "r"(b[1]));
}
#define CP16(sm, gm) \
    asm volatile("cp.async.cg.shared.global [%0], [%1], 16;" :: "r"(sm), "l"(gm))
#define CPCOMMIT() asm volatile("cp.async.commit_group;" ::: "memory")
#define CPWAIT(n)  asm volatile("cp.async.wait_group %0;" :: "n"(n) : "memory")

__device__ __forceinline__ uint32_t bfu(bf16 h) {
    return (uint32_t)__bfloat16_as_ushort(h);
}
__device__ __forceinline__ void split1(float v, bf16& h, bf16& l) {
    h = __float2bfloat16_rn(v);
    l = __float2bfloat16_rn(v - __bfloat162float(h));
}
__device__ __forceinline__ void split2(float a, float b, uint32_t& hp, uint32_t& lp) {
    bf16 ha, la, hb, lb;
    split1(a, ha, la); split1(b, hb, lb);
    hp = (bfu(hb) << 16) | bfu(ha);
    lp = (bfu(lb) << 16) | bfu(la);
}

// ------------------------- bf16x3 TN GEMM kernel ---------------------------
// C[128x128 tile] = alpha * (Ah+Al)[M,K] x (Bh+Bl)[N,K]^T
//   EPI 0: C fp32 * alpha ; EPI 1: C fp32 + R ; EPI 2: C -> bf16 hi/lo
// Smem stage (BK=32): 4 tiles (Ah, Al, Bh, Bl) of 128 rows x 80B (64B + pad)
static constexpr int RSTRIDE   = 80;
static constexpr int TILE_B    = 128 * RSTRIDE;   // 10240
static constexpr int STAGE_B   = 4 * TILE_B;      // 40960
static constexpr int GEMM_SMEM = 2 * STAGE_B;     // 81920

template<int EPI>
__global__ void __launch_bounds__(256, 2)
gemm_bf3(const bf16* __restrict__ Ah, const bf16* __restrict__ Al,
         const bf16* __restrict__ Bh, const bf16* __restrict__ Bl,
         const float* __restrict__ R, float* __restrict__ C,
         bf16* __restrict__ Ch, bf16* __restrict__ Cl,
         int K, int lda, int ldb, int ldc,
         int64_t sA1, int64_t sA2, int64_t sB1, int64_t sB2,
         int64_t sC1, int64_t sC2, int nz2, float alpha)
{
    extern __shared__ uint8_t sm[];
    uint32_t smb = smem_u32(sm);

    int tid  = threadIdx.x;
    int lane = tid & 31;
    int w    = tid >> 5;
    int wm   = w & 1;          // 2 m-blocks of 64
    int wn   = w >> 1;         // 4 n-blocks of 32

    int z = blockIdx.z, z1 = z / nz2, z2 = z - z1 * nz2;
    int64_t offA = z1 * sA1 + z2 * sA2;
    int64_t offB = z1 * sB1 + z2 * sB2;
    int64_t offC = z1 * sC1 + z2 * sC2;

    int64_t rowBase = (int64_t)blockIdx.y * 128;
    int64_t colBase = (int64_t)blockIdx.x * 128;

    const bf16* AhB = Ah + offA + rowBase * lda;
    const bf16* AlB = Al + offA + rowBase * lda;
    const bf16* BhB = Bh + offB + colBase * ldb;
    const bf16* BlB = Bl + offB + colBase * ldb;

    uint32_t aRowOff = (uint32_t)((wm * 64 + (lane & 15)) * RSTRIDE
                                  + ((lane >> 4) & 1) * 16);
    uint32_t bRowOff = (uint32_t)((wn * 32 + (lane & 7) + ((lane >> 4) & 1) * 8) * RSTRIDE
                                  + ((lane >> 3) & 1) * 16);

    float acc[4][4][4];
    #pragma unroll
    for (int i = 0; i < 4; i++)
        #pragma unroll
        for (int j = 0; j < 4; j++)
            #pragma unroll
            for (int e = 0; e < 4; e++) acc[i][j][e] = 0.f;

    int nT = K / 32;

    // cp.async one stage: 4 tiles x 128 rows x 64B; 8 CP16 per thread
    auto issue_stage = [&](int t, int buf) {
        int kk0 = t * 32;
        uint32_t sb = smb + buf * STAGE_B;
        #pragma unroll
        for (int i = 0; i < 2; i++) {
            int ch  = tid + i * 256;
            int row = ch >> 2, c = ch & 3;
            uint32_t so = (uint32_t)(row * RSTRIDE + c * 16);
            int64_t  ga = (int64_t)row * lda + kk0 + c * 8;
            int64_t  gb = (int64_t)row * ldb + kk0 + c * 8;
            CP16(sb + so,              AhB + ga);
            CP16(sb + TILE_B + so,     AlB + ga);
            CP16(sb + 2 * TILE_B + so, BhB + gb);
            CP16(sb + 3 * TILE_B + so, BlB + gb);
        }
        CPCOMMIT();
    };

    // compute one stage: 2 k16-steps x {hi*hi, hi*lo, lo*hi}
    auto compute = [&](int buf) {
        uint32_t stB = smb + buf * STAGE_B;
        #pragma unroll
        for (int ks = 0; ks < 2; ks++) {
            uint32_t aAd = stB + aRowOff + ks * 32;
            uint32_t bAd = stB + 2 * TILE_B + bRowOff + ks * 32;
            uint32_t aF[16], bH[8], bL[8];
            ldm4(aAd,            aF);
            ldm4(aAd + 1 * 1280, aF + 4);
            ldm4(aAd + 2 * 1280, aF + 8);
            ldm4(aAd + 3 * 1280, aF + 12);
            ldm4(bAd,        bH);
            ldm4(bAd + 1280, bH + 4);
            #pragma unroll
            for (int i = 0; i < 4; i++)
                #pragma unroll
                for (int j = 0; j < 4; j++)
                    mma16816(acc[i][j], aF + 4 * i, bH + 2 * j);
            ldm4(bAd + TILE_B,        bL);
            ldm4(bAd + TILE_B + 1280, bL + 4);
            #pragma unroll
            for (int i = 0; i < 4; i++)
                #pragma unroll
                for (int j = 0; j < 4; j++)
                    mma16816(acc[i][j], aF + 4 * i, bL + 2 * j);
            ldm4(aAd + TILE_B,            aF);
            ldm4(aAd + TILE_B + 1 * 1280, aF + 4);
            ldm4(aAd + TILE_B + 2 * 1280, aF + 8);
            ldm4(aAd + TILE_B + 3 * 1280, aF + 12);
            #pragma unroll
            for (int i = 0; i < 4; i++)
                #pragma unroll
                for (int j = 0; j < 4; j++)
                    mma16816(acc[i][j], aF + 4 * i, bH + 2 * j);
        }
    };

    // ---- 2-stage cp.async pipeline ----
    issue_stage(0, 0);
    for (int t = 0; t < nT; t++) {
        if (t + 1 < nT) {
            issue_stage(t + 1, (t + 1) & 1);
            CPWAIT(1);
        } else {
            CPWAIT(0);
        }
        __syncthreads();
        compute(t & 1);
        __syncthreads();
    }

    // ---- epilogue ----
    int lrow = lane >> 2;
    int lcol = (lane & 3) * 2;
    #pragma unroll
    for (int i = 0; i < 4; i++) {
        int64_t r0 = rowBase + wm * 64 + i * 16 + lrow;
        #pragma unroll
        for (int j = 0; j < 4; j++) {
            int64_t c = colBase + wn * 32 + j * 8 + lcol;
            int64_t o0 = (offC + r0 * ldc + c);
            int64_t o1 = o0 + 8 * ldc;
            if (EPI == 0) {
                float2 p0, p1;
                p0.x = acc[i][j][0] * alpha; p0.y = acc[i][j][1] * alpha;
                p1.x = acc[i][j][2] * alpha; p1.y = acc[i][j][3] * alpha;
                *(float2*)(C + o0) = p0;
                *(float2*)(C + o1) = p1;
            } else if (EPI == 1) {
                float2 ra = *(const float2*)(R + o0);
                float2 rb = *(const float2*)(R + o1);
                float2 p0, p1;
                p0.x = acc[i][j][0] + ra.x; p0.y = acc[i][j][1] + ra.y;
                p1.x = acc[i][j][2] + rb.x; p1.y = acc[i][j][3] + rb.y;
                *(float2*)(C + o0) = p0;
                *(float2*)(C + o1) = p1;
            } else {
                uint32_t hp, lp;
                split2(acc[i][j][0], acc[i][j][1], hp, lp);
                *(uint32_t*)(Ch + o0) = hp;
                *(uint32_t*)(Cl + o0) = lp;
                split2(acc[i][j][2], acc[i][j][3], hp, lp);
                *(uint32_t*)(Ch + o1) = hp;
                *(uint32_t*)(Cl + o1) = lp;
            }
        }
    }
}

// ------------------------------ reductions ---------------------------------
__device__ __forceinline__ float warp_sum(float v) {
    #pragma unroll
    for (int o = 16; o > 0; o >>= 1) v += __shfl_xor_sync(0xffffffffu, v, o);
    return v;
}
__device__ __forceinline__ float warp_max(float v) {
    #pragma unroll
    for (int o = 16; o > 0; o >>= 1) v = fmaxf(v, __shfl_xor_sync(0xffffffffu, v, o));
    return v;
}

// ------------------------- weight split (fp32 -> hi/lo) --------------------
__global__ void __launch_bounds__(256)
split_kernel(const float* __restrict__ in, bf16* __restrict__ oh,
             bf16* __restrict__ ol)
{
    size_t i = ((size_t)blockIdx.x * 256 + threadIdx.x) * 4;
    float4 v = *(const float4*)(in + i);
    uint32_t h0, l0, h1, l1;
    split2(v.x, v.y, h0, l0);
    split2(v.z, v.w, h1, l1);
    *(uint2*)(oh + i) = make_uint2(h0, h1);
    *(uint2*)(ol + i) = make_uint2(l0, l1);
}

// ------------------------------- LayerNorm ---------------------------------
__global__ void __launch_bounds__(256)
ln_kernel(const float* __restrict__ x, const float* __restrict__ w,
          const float* __restrict__ b, bf16* __restrict__ yh,
          bf16* __restrict__ yl)
{
    __shared__ float s1[8], s2[8];
    size_t row = blockIdx.x;
    const float* xr = x + row * (size_t)D_;

    float vals[8];
    float sum = 0.f, sq = 0.f;
    #pragma unroll
    for (int i = 0; i < 8; i++) {
        float v = xr[threadIdx.x + i * 256];
        vals[i] = v; sum += v; sq += v * v;
    }
    sum = warp_sum(sum); sq = warp_sum(sq);
    int wi = threadIdx.x >> 5, li = threadIdx.x & 31;
    if (li == 0) { s1[wi] = sum; s2[wi] = sq; }
    __syncthreads();
    float ts = 0.f, tq = 0.f;
    #pragma unroll
    for (int i = 0; i < 8; i++) { ts += s1[i]; tq += s2[i]; }
    float mean = ts * (1.f / D_);
    float var  = tq * (1.f / D_) - mean * mean;
    float rstd = rsqrtf(var + LN_EPS);
    #pragma unroll
    for (int i = 0; i < 8; i++) {
        int c = threadIdx.x + i * 256;
        float y = (vals[i] - mean) * rstd * w[c] + b[c];
        bf16 h, l; split1(y, h, l);
        yh[row * (size_t)D_ + c] = h;
        yl[row * (size_t)D_ + c] = l;
    }
}

// ------------------------------- Softmax -----------------------------------
__global__ void __launch_bounds__(256)
softmax_kernel(const float* __restrict__ s, bf16* __restrict__ ph,
               bf16* __restrict__ pl)
{
    __shared__ float sm1[8], sm2[8];
    size_t row = blockIdx.x;
    const float* p = s + row * (size_t)T_;

    float v[8];
    float mx = -1e30f;
    #pragma unroll
    for (int i = 0; i < 8; i++) { v[i] = p[threadIdx.x + i * 256]; mx = fmaxf(mx, v[i]); }
    mx = warp_max(mx);
    int wi = threadIdx.x >> 5, li = threadIdx.x & 31;
    if (li == 0) sm1[wi] = mx;
    __syncthreads();
    float tmx = -1e30f;
    #pragma unroll
    for (int i = 0; i < 8; i++) tmx = fmaxf(tmx, sm1[i]);

    float sum = 0.f;
    #pragma unroll
    for (int i = 0; i < 8; i++) { v[i] = __expf(v[i] - tmx); sum += v[i]; }
    sum = warp_sum(sum);
    if (li == 0) sm2[wi] = sum;
    __syncthreads();
    float tsum = 0.f;
    #pragma unroll
    for (int i = 0; i < 8; i++) tsum += sm2[i];
    float inv = 1.f / tsum;
    #pragma unroll
    for (int i = 0; i < 8; i++) {
        int c = threadIdx.x + i * 256;
        bf16 h, l; split1(v[i] * inv, h, l);
        ph[row * (size_t)T_ + c] = h;
        pl[row * (size_t)T_ + c] = l;
    }
}

// ------------------------------ SiLU * up ----------------------------------
// gu layout: [M, 2F] fp32, row = gate[0:F] | up[F:2F]
__global__ void __launch_bounds__(256)
silu_mul_kernel(const float* __restrict__ gu, bf16* __restrict__ hh,
                bf16* __restrict__ hl)
{
    size_t idx = ((size_t)blockIdx.x * 256 + threadIdx.x) * 4;   // in [0, M*F)
    size_t row = idx / F_;
    size_t c   = idx - row * F_;
    const float* g = gu + row * (size_t)(2 * F_) + c;
    const float* u = g + F_;
    float4 gg = *(const float4*)g;
    float4 uu = *(const float4*)u;
    float4 o;
    o.x = gg.x * (1.f / (1.f + __expf(-gg.x))) * uu.x;
    o.y = gg.y * (1.f / (1.f + __expf(-gg.y))) * uu.y;
    o.z = gg.z * (1.f / (1.f + __expf(-gg.z))) * uu.z;
    o.w = gg.w * (1.f / (1.f + __expf(-gg.w))) * uu.w;
    uint32_t h0, l0, h1, l1;
    split2(o.x, o.y, h0, l0);
    split2(o.z, o.w, h1, l1);
    *(uint2*)(hh + idx) = make_uint2(h0, h1);
    *(uint2*)(hl + idx) = make_uint2(l0, l1);
}

// --------------------------- V transpose -----------------------------------
// v rows at stride ldv (view into qkv), v[b, t, h*128+d] -> vt[(b*H+h)*128+d][t]
__global__ void __launch_bounds__(256)
transpose_v_kernel(const bf16* __restrict__ vh, const bf16* __restrict__ vl,
                   bf16* __restrict__ vth, bf16* __restrict__ vtl, int ldv)
{
    __shared__ bf16 th[32][33], tl[32][33];
    int t0 = blockIdx.x * 32;
    int d0 = blockIdx.y * 32;
    int bb = blockIdx.z;
    int tx = threadIdx.x & 31, ty = threadIdx.x >> 5;  // 32 x 8

    #pragma unroll
    for (int kq = 0; kq < 4; kq++) {
        int y = ty + kq * 8;     // local t
        size_t gi = ((size_t)bb * T_ + t0 + y) * ldv + d0 + tx;
        th[y][tx] = vh[gi];
        tl[y][tx] = vl[gi];
    }
    __syncthreads();
    #pragma unroll
    for (int kq = 0; kq < 4; kq++) {
        int y = ty + kq * 8;     // local d
        int d = d0 + y;
        int h = d >> 7, dd = d & 127;
        size_t go = (((size_t)bb * H_ + h) * 128 + dd) * T_ + t0 + tx;
        vth[go] = th[tx][y];
        vtl[go] = tl[tx][y];
    }
}

// ------------------------------ launcher -----------------------------------
extern "C" void kernel_launch(void* const* d_in, const int* in_sizes, int n_in,
                              void* d_out, int out_size)
{
    const float* x    = (const float*)d_in[0];
    const float* wq   = (const float*)d_in[1];
    const float* wk   = (const float*)d_in[2];
    const float* wv   = (const float*)d_in[3];
    const float* wo   = (const float*)d_in[4];
    const float* wgt  = (const float*)d_in[5];
    const float* wup  = (const float*)d_in[6];
    const float* wdn  = (const float*)d_in[7];
    const float* ln1w = (const float*)d_in[8];
    const float* ln1b = (const float*)d_in[9];
    const float* ln2w = (const float*)d_in[10];
    const float* ln2b = (const float*)d_in[11];
    float* out = (float*)d_out;

    bf16 *wqkvh, *wqkvl, *woh, *wol, *wguh, *wgul, *wdh, *wdl;
    bf16 *xnh, *xnl, *qkvh, *qkvl, *vth, *vtl, *ath, *atl, *hh, *hl, *ph, *pl;
    float *s, *x1, *gu;
    cudaGetSymbolAddress((void**)&wqkvh, g_wqkvh); cudaGetSymbolAddress((void**)&wqkvl, g_wqkvl);
    cudaGetSymbolAddress((void**)&woh,   g_woh);   cudaGetSymbolAddress((void**)&wol,   g_wol);
    cudaGetSymbolAddress((void**)&wguh,  g_wguh);  cudaGetSymbolAddress((void**)&wgul,  g_wgul);
    cudaGetSymbolAddress((void**)&wdh,   g_wdh);   cudaGetSymbolAddress((void**)&wdl,   g_wdl);
    cudaGetSymbolAddress((void**)&xnh,   g_xnh);   cudaGetSymbolAddress((void**)&xnl,   g_xnl);
    cudaGetSymbolAddress((void**)&qkvh,  g_qkvh);  cudaGetSymbolAddress((void**)&qkvl,  g_qkvl);
    cudaGetSymbolAddress((void**)&vth,   g_vth);   cudaGetSymbolAddress((void**)&vtl,   g_vtl);
    cudaGetSymbolAddress((void**)&ath,   g_ath);   cudaGetSymbolAddress((void**)&atl,   g_atl);
    cudaGetSymbolAddress((void**)&hh,    g_hh);    cudaGetSymbolAddress((void**)&hl,    g_hl);
    cudaGetSymbolAddress((void**)&ph,    g_ph);    cudaGetSymbolAddress((void**)&pl,    g_pl);
    cudaGetSymbolAddress((void**)&s,     g_s);     cudaGetSymbolAddress((void**)&x1,    g_x1);
    cudaGetSymbolAddress((void**)&gu,    g_gu);

    cudaFuncSetAttribute(gemm_bf3<0>, cudaFuncAttributeMaxDynamicSharedMemorySize, GEMM_SMEM);
    cudaFuncSetAttribute(gemm_bf3<1>, cudaFuncAttributeMaxDynamicSharedMemorySize, GEMM_SMEM);
    cudaFuncSetAttribute(gemm_bf3<2>, cudaFuncAttributeMaxDynamicSharedMemorySize, GEMM_SMEM);

    const int64_t TT  = (int64_t)T_ * T_;
    const int64_t DD  = (int64_t)D_ * D_;
    const int64_t FD  = (int64_t)F_ * D_;
    const int64_t LD3 = 3 * (int64_t)D_;          // qkv row stride

    // 0. split weights (QKV and gate/up land in concatenated buffers)
    split_kernel<<<(int)(DD / 1024), 256>>>(wq,  wqkvh,          wqkvl);
    split_kernel<<<(int)(DD / 1024), 256>>>(wk,  wqkvh + DD,     wqkvl + DD);
    split_kernel<<<(int)(DD / 1024), 256>>>(wv,  wqkvh + 2 * DD, wqkvl + 2 * DD);
    split_kernel<<<(int)(DD / 1024), 256>>>(wo,  woh, wol);
    split_kernel<<<(int)(FD / 1024), 256>>>(wgt, wguh,      wgul);
    split_kernel<<<(int)(FD / 1024), 256>>>(wup, wguh + FD, wgul + FD);
    split_kernel<<<(int)(FD / 1024), 256>>>(wdn, wdh, wdl);

    // 1. LN1
    ln_kernel<<<MTOK, 256>>>(x, ln1w, ln1b, xnh, xnl);

    // 2. fused QKV projection: qkv[M, 3D] = xn @ wqkv^T
    {
        dim3 grid(3 * D_ / 128, MTOK / 128, 1);
        gemm_bf3<2><<<grid, 256, GEMM_SMEM>>>(xnh, xnl, wqkvh, wqkvl, nullptr, nullptr,
            qkvh, qkvl, D_, D_, D_, (int)LD3, 0, 0, 0, 0, 0, 0, 1, 1.f);
    }

    // 2b. transpose V view -> vt [b,h,d,t]
    {
        dim3 grid(T_ / 32, D_ / 32, B_);
        transpose_v_kernel<<<grid, 256>>>(qkvh + 2 * D_, qkvl + 2 * D_,
                                          vth, vtl, (int)LD3);
    }

    // 3. scores = Q K^T / sqrt(Dh)   (Q, K are strided views of qkv)
    {
        dim3 grid(T_ / 128, T_ / 128, B_ * H_);
        gemm_bf3<0><<<grid, 256, GEMM_SMEM>>>(qkvh, qkvl, qkvh + D_, qkvl + D_,
            nullptr, s, nullptr, nullptr, DH_, (int)LD3, (int)LD3, T_,
            (int64_t)T_ * LD3, DH_, (int64_t)T_ * LD3, DH_,
            (int64_t)H_ * TT, TT, H_,
            0.08838834764831845f);
    }

    // 4. softmax -> p hi/lo
    softmax_kernel<<<B_ * H_ * T_, 256>>>(s, ph, pl);

    // 5. attn_out = P @ V  (TN with vt)
    {
        dim3 grid(1, T_ / 128, B_ * H_);
        gemm_bf3<2><<<grid, 256, GEMM_SMEM>>>(ph, pl, vth, vtl, nullptr, nullptr,
            ath, atl, T_, T_, T_, D_,
            (int64_t)H_ * TT, TT, (int64_t)H_ * DH_ * T_, (int64_t)DH_ * T_,
            (int64_t)T_ * D_, DH_, H_, 1.f);
    }

    // 6. x1 = at @ wo^T + x
    {
        dim3 grid(D_ / 128, MTOK / 128, 1);
        gemm_bf3<1><<<grid, 256, GEMM_SMEM>>>(ath, atl, woh, wol, x, x1,
            nullptr, nullptr, D_, D_, D_, D_, 0, 0, 0, 0, 0, 0, 1, 1.f);
    }

    // 7. LN2
    ln_kernel<<<MTOK, 256>>>(x1, ln2w, ln2b, xnh, xnl);

    // 8. fused gate|up: gu[M, 2F] = xn @ wgu^T
    {
        dim3 grid(2 * F_ / 128, MTOK / 128, 1);
        gemm_bf3<0><<<grid, 256, GEMM_SMEM>>>(xnh, xnl, wguh, wgul, nullptr, gu,
            nullptr, nullptr, D_, D_, D_, 2 * F_, 0, 0, 0, 0, 0, 0, 1, 1.f);
    }

    // 9. h = silu(gate) * up -> hi/lo
    silu_mul_kernel<<<(int)(((size_t)MTOK * F_) / 1024), 256>>>(gu, hh, hl);

    // 10. out = h @ wdn^T + x1
    {
        dim3 grid(D_ / 128, MTOK / 128, 1);
        gemm_bf3<1><<<grid, 256, GEMM_SMEM>>>(hh, hl, wdh, wdl, x1, out,
            nullptr, nullptr, F_, F_, F_, D_, 0, 0, 0, 0, 0, 0, 1, 1.f);
    }
}